// round 15
// baseline (speedup 1.0000x reference)
#include <cuda_runtime.h>
#include <cuda_bf16.h>
#include <cuda/atomic>

#define NUM_P 41                // pred labels 0..40
#define NUM_C 26                // gt labels 0..25
#define BINS  (NUM_P * NUM_C)   // 1066
#define PB    BINS              // pair-table dimension
#define TBL   (PB * PB)         // 1,136,356 u32 = 4.5 MB (L2-resident)
#define HIST_BLOCKS 148         // one block per SM -> all co-resident (spin-safe)
#define HIST_THREADS 1024

// Pair table: one global RED.ADD records TWO voxels (row = bin of voxel A,
// col = bin of voxel B). counts[k] = rowsum_k + colsum_k, recovered in phase 2.
// All scratch zero at module load; re-zeroed in-kernel each run (replay-safe).
__device__ unsigned int g_pair[TBL];
__device__ unsigned int g_cnt[BINS];   // final joint histogram
__device__ unsigned int g_t1, g_t2;    // phase barriers / winner election

__device__ __forceinline__ unsigned int block_reduce_add(unsigned int v) {
    __shared__ unsigned int sred[32];
    const unsigned int lane = threadIdx.x & 31u, w = threadIdx.x >> 5;
    #pragma unroll
    for (int o = 16; o > 0; o >>= 1) v += __shfl_down_sync(0xFFFFFFFFu, v, o);
    if (lane == 0) sred[w] = v;
    __syncthreads();
    if (w == 0) {
        v = sred[lane];
        #pragma unroll
        for (int o = 16; o > 0; o >>= 1) v += __shfl_down_sync(0xFFFFFFFFu, v, o);
    }
    __syncthreads();   // sred reusable next call
    return v;          // valid in thread 0
}

// Finalize: identical math to the validated version, reading g_cnt.
__device__ __noinline__ void finalize_body(float* __restrict__ out) {
    __shared__ float        s_pred_sizes[NUM_P];
    __shared__ unsigned int s_omask[NUM_P];
    __shared__ float        s_gt_sizes[NUM_C];
    __shared__ unsigned int s_present;
    __shared__ float        s_dice[64];
    __shared__ float        s_fp[64];

    const int t = threadIdx.x;

    if (t < NUM_P) {
        float ps = 0.0f;
        unsigned int m = 0u;
        #pragma unroll
        for (int c = 0; c < NUM_C; c++) {
            unsigned int v = g_cnt[t * NUM_C + c];
            ps += (float)v;
            if (c >= 1 && v) m |= (1u << c);
        }
        s_pred_sizes[t] = ps;
        s_omask[t] = m;
    }
    if (t < NUM_C) {
        float gs = 0.0f;
        #pragma unroll
        for (int p = 0; p < NUM_P; p++)
            gs += (float)g_cnt[p * NUM_C + t];
        s_gt_sizes[t] = gs;
    }
    __syncthreads();

    if (t == 0) {
        unsigned int pm = 0u;
        for (int c = 1; c < NUM_C; c++)
            if (s_gt_sizes[c] > 0.0f) pm |= (1u << c);
        s_present = pm;
    }
    __syncthreads();
    const unsigned int pm = s_present;

    if (t < 64) {
        float contrib = 0.0f;
        if (t >= 1 && t < NUM_C && ((pm >> t) & 1u)) {
            float us = 0.0f;
            #pragma unroll
            for (int p = 0; p < NUM_P; p++)
                if ((s_omask[p] >> t) & 1u) us += s_pred_sizes[p];
            contrib = 2.0f * s_gt_sizes[t] / (us + s_gt_sizes[t] + 1.0f);
        }
        float fpc = 0.0f;
        if (t < NUM_P && s_pred_sizes[t] > 0.0f && (s_omask[t] & pm) == 0u)
            fpc = 1.0f;
        s_dice[t] = contrib;
        s_fp[t]   = fpc;
    }
    __syncthreads();

    if (t == 0) {
        float lesion_dice = 0.0f, fp = 0.0f;
        for (int k = 0; k < 64; k++) { lesion_dice += s_dice[k]; fp += s_fp[k]; }
        float num_gt = (float)__popc(pm);
        out[0] = lesion_dice / (num_gt + fp);
    }
    __syncthreads();

    // Reset remaining scratch for the next graph replay.
    for (int k = t; k < BINS; k += HIST_THREADS) g_cnt[k] = 0u;
    if (t == 0) { g_t1 = 0u; g_t2 = 0u; }
}

__global__ void __launch_bounds__(HIST_THREADS)
fused_kernel(const float4* __restrict__ pred4, const int4* __restrict__ gt4,
             const float* __restrict__ pred, const int* __restrict__ gt,
             int n4, int n, float* __restrict__ out) {
    const int t = threadIdx.x;
    const int stride = gridDim.x * HIST_THREADS;
    int i = blockIdx.x * HIST_THREADS + t;

    // ---- Phase 1: pair-binned global RED.ADD, 0.5 atomics/voxel ----
    for (; i + stride < n4; i += 2 * stride) {
        float4 p0 = pred4[i];
        int4   g0 = gt4[i];
        float4 p1 = pred4[i + stride];
        int4   g1 = gt4[i + stride];
        int b0 = __float2int_rn(p0.x) * NUM_C + g0.x;
        int b1 = __float2int_rn(p0.y) * NUM_C + g0.y;
        int b2 = __float2int_rn(p0.z) * NUM_C + g0.z;
        int b3 = __float2int_rn(p0.w) * NUM_C + g0.w;
        int b4 = __float2int_rn(p1.x) * NUM_C + g1.x;
        int b5 = __float2int_rn(p1.y) * NUM_C + g1.y;
        int b6 = __float2int_rn(p1.z) * NUM_C + g1.z;
        int b7 = __float2int_rn(p1.w) * NUM_C + g1.w;
        atomicAdd(&g_pair[b0 * PB + b1], 1u);
        atomicAdd(&g_pair[b2 * PB + b3], 1u);
        atomicAdd(&g_pair[b4 * PB + b5], 1u);
        atomicAdd(&g_pair[b6 * PB + b7], 1u);
    }
    for (; i < n4; i += stride) {
        float4 p = pred4[i];
        int4   g = gt4[i];
        int b0 = __float2int_rn(p.x) * NUM_C + g.x;
        int b1 = __float2int_rn(p.y) * NUM_C + g.y;
        int b2 = __float2int_rn(p.z) * NUM_C + g.z;
        int b3 = __float2int_rn(p.w) * NUM_C + g.w;
        atomicAdd(&g_pair[b0 * PB + b1], 1u);
        atomicAdd(&g_pair[b2 * PB + b3], 1u);
    }
    // scalar tail: single voxels go straight into g_cnt (phase 2 adds on top)
    int tail_start = n4 * 4;
    for (int j = tail_start + blockIdx.x * HIST_THREADS + t; j < n; j += stride)
        atomicAdd(&g_cnt[__float2int_rn(pred[j]) * NUM_C + gt[j]], 1u);

    // ---- Grid barrier 1 (all blocks resident: grid == #SMs) ----
    __shared__ unsigned int s_go;
    if (t == 0) {
        cuda::atomic_ref<unsigned int, cuda::thread_scope_device> tk(g_t1);
        tk.fetch_add(1u, cuda::memory_order_acq_rel);
        while (tk.load(cuda::memory_order_acquire) < (unsigned)gridDim.x)
            __nanosleep(128);
        s_go = 1u;
    }
    __syncthreads();
    (void)s_go;

    // ---- Phase 2: reduce pair table -> g_cnt, zeroing as we sweep ----
    // Rows strided across blocks; within a row, thread t covers col t (and
    // col 1024+t for t<42). Column partials accumulate in registers.
    unsigned int colA = 0u, colB = 0u;
    for (int r = blockIdx.x; r < PB; r += gridDim.x) {
        unsigned int* row = &g_pair[r * PB];
        unsigned int v0 = row[t];
        row[t] = 0u;
        unsigned int rowpart = v0;
        colA += v0;
        if (t < PB - 1024) {
            unsigned int v1 = row[1024 + t];
            row[1024 + t] = 0u;
            rowpart += v1;
            colB += v1;
        }
        unsigned int rowtotal = block_reduce_add(rowpart);
        if (t == 0 && rowtotal) atomicAdd(&g_cnt[r], rowtotal);
    }
    if (colA) atomicAdd(&g_cnt[t], colA);
    if (t < PB - 1024 && colB) atomicAdd(&g_cnt[1024 + t], colB);

    // ---- Barrier 2 + winner election ----
    __shared__ unsigned int s_last;
    if (t == 0) {
        cuda::atomic_ref<unsigned int, cuda::thread_scope_device> tk(g_t2);
        s_last = (tk.fetch_add(1u, cuda::memory_order_acq_rel)
                  == (unsigned)gridDim.x - 1u) ? 1u : 0u;
    }
    __syncthreads();
    if (!s_last) return;

    finalize_body(out);
}

extern "C" void kernel_launch(void* const* d_in, const int* in_sizes, int n_in,
                              void* d_out, int out_size) {
    const float* pred = (const float*)d_in[0];
    const int*   gt   = (const int*)d_in[1];
    float* out = (float*)d_out;
    const int n  = in_sizes[0];
    const int n4 = n >> 2;

    fused_kernel<<<HIST_BLOCKS, HIST_THREADS>>>(
        (const float4*)pred, (const int4*)gt, pred, gt, n4, n, out);
}

// round 16
// speedup vs baseline: 2.6169x; 2.6169x over previous
#include <cuda_runtime.h>
#include <cuda_bf16.h>
#include <cuda/atomic>

#define NUM_P 41          // pred labels 0..40
#define NUM_C 26          // gt labels 0..25
#define BINS  (NUM_P * NUM_C)   // 1066
#define PAIRS (BINS / 2)        // 533
#define HIST_BLOCKS 148         // one block per SM
#define HIST_THREADS 1024

// Global scratch: bin pairs packed into u64 (lo = bin 2k, hi = bin 2k+1).
// Zero at module load; the winning block re-zeroes after use so graph replays
// start clean. Per-bin totals <= 2^24 so no carry crosses the 32-bit boundary.
__device__ unsigned long long g_counts64[PAIRS];
__device__ unsigned int g_ticket;

// Separate ABI allocation: keeps the epilogue's registers/codegen out of the
// hot mainloop. Runs once, on one block, after the ticket election.
__device__ __noinline__ void finalize_body(float* __restrict__ out) {
    __shared__ float        s_pred_sizes[NUM_P];
    __shared__ unsigned int s_omask[NUM_P];
    __shared__ float        s_gt_sizes[NUM_C];
    __shared__ unsigned int s_present;
    __shared__ float        s_dice[64];
    __shared__ float        s_fp[64];

    const int t = threadIdx.x;
    const unsigned int* gc = (const unsigned int*)g_counts64;  // bin k at gc[k]

    if (t < NUM_P) {
        float ps = 0.0f;
        unsigned int m = 0u;
        #pragma unroll
        for (int c = 0; c < NUM_C; c++) {
            unsigned int v = gc[t * NUM_C + c];
            ps += (float)v;
            if (c >= 1 && v) m |= (1u << c);
        }
        s_pred_sizes[t] = ps;
        s_omask[t] = m;
    }
    if (t < NUM_C) {
        float gs = 0.0f;
        #pragma unroll
        for (int p = 0; p < NUM_P; p++)
            gs += (float)gc[p * NUM_C + t];
        s_gt_sizes[t] = gs;
    }
    __syncthreads();

    if (t == 0) {
        unsigned int pm = 0u;
        for (int c = 1; c < NUM_C; c++)
            if (s_gt_sizes[c] > 0.0f) pm |= (1u << c);
        s_present = pm;
    }
    __syncthreads();
    const unsigned int pm = s_present;

    if (t < 64) {
        float contrib = 0.0f;
        if (t >= 1 && t < NUM_C && ((pm >> t) & 1u)) {
            float us = 0.0f;
            #pragma unroll
            for (int p = 0; p < NUM_P; p++)
                if ((s_omask[p] >> t) & 1u) us += s_pred_sizes[p];
            contrib = 2.0f * s_gt_sizes[t] / (us + s_gt_sizes[t] + 1.0f);
        }
        float fpc = 0.0f;
        if (t < NUM_P && s_pred_sizes[t] > 0.0f && (s_omask[t] & pm) == 0u)
            fpc = 1.0f;
        s_dice[t] = contrib;
        s_fp[t]   = fpc;
    }
    __syncthreads();

    if (t == 0) {
        float lesion_dice = 0.0f, fp = 0.0f;
        for (int k = 0; k < 64; k++) { lesion_dice += s_dice[k]; fp += s_fp[k]; }
        float num_gt = (float)__popc(pm);
        out[0] = lesion_dice / (num_gt + fp);
    }
    __syncthreads();

    // Reset scratch for the next graph replay (deterministic across runs).
    for (int k = t; k < PAIRS; k += HIST_THREADS) g_counts64[k] = 0ull;
    if (t == 0) g_ticket = 0u;
}

__global__ void __launch_bounds__(HIST_THREADS)
fused_kernel(const float4* __restrict__ pred4, const int4* __restrict__ gt4,
             const float* __restrict__ pred, const int* __restrict__ gt,
             int n4, int n, float* __restrict__ out) {
    __shared__ unsigned int h[BINS];
    for (int i = threadIdx.x; i < BINS; i += HIST_THREADS) h[i] = 0u;
    __syncthreads();

    const int stride = gridDim.x * HIST_THREADS;
    int i = blockIdx.x * HIST_THREADS + threadIdx.x;

    // Main loop: 4 float4 + 4 int4 loads in flight (MLP 8), 1 ATOMS/voxel,
    // 16 voxels per thread-iteration (amortized loop overhead).
    for (; i + 3 * stride < n4; i += 4 * stride) {
        float4 p0 = pred4[i];
        float4 p1 = pred4[i + stride];
        float4 p2 = pred4[i + 2 * stride];
        float4 p3 = pred4[i + 3 * stride];
        int4   g0 = gt4[i];
        int4   g1 = gt4[i + stride];
        int4   g2 = gt4[i + 2 * stride];
        int4   g3 = gt4[i + 3 * stride];
        atomicAdd(&h[__float2int_rn(p0.x) * NUM_C + g0.x], 1u);
        atomicAdd(&h[__float2int_rn(p0.y) * NUM_C + g0.y], 1u);
        atomicAdd(&h[__float2int_rn(p0.z) * NUM_C + g0.z], 1u);
        atomicAdd(&h[__float2int_rn(p0.w) * NUM_C + g0.w], 1u);
        atomicAdd(&h[__float2int_rn(p1.x) * NUM_C + g1.x], 1u);
        atomicAdd(&h[__float2int_rn(p1.y) * NUM_C + g1.y], 1u);
        atomicAdd(&h[__float2int_rn(p1.z) * NUM_C + g1.z], 1u);
        atomicAdd(&h[__float2int_rn(p1.w) * NUM_C + g1.w], 1u);
        atomicAdd(&h[__float2int_rn(p2.x) * NUM_C + g2.x], 1u);
        atomicAdd(&h[__float2int_rn(p2.y) * NUM_C + g2.y], 1u);
        atomicAdd(&h[__float2int_rn(p2.z) * NUM_C + g2.z], 1u);
        atomicAdd(&h[__float2int_rn(p2.w) * NUM_C + g2.w], 1u);
        atomicAdd(&h[__float2int_rn(p3.x) * NUM_C + g3.x], 1u);
        atomicAdd(&h[__float2int_rn(p3.y) * NUM_C + g3.y], 1u);
        atomicAdd(&h[__float2int_rn(p3.z) * NUM_C + g3.z], 1u);
        atomicAdd(&h[__float2int_rn(p3.w) * NUM_C + g3.w], 1u);
    }
    for (; i < n4; i += stride) {
        float4 p = pred4[i];
        int4   g = gt4[i];
        atomicAdd(&h[__float2int_rn(p.x) * NUM_C + g.x], 1u);
        atomicAdd(&h[__float2int_rn(p.y) * NUM_C + g.y], 1u);
        atomicAdd(&h[__float2int_rn(p.z) * NUM_C + g.z], 1u);
        atomicAdd(&h[__float2int_rn(p.w) * NUM_C + g.w], 1u);
    }
    int tail_start = n4 * 4;
    for (int j = tail_start + blockIdx.x * HIST_THREADS + threadIdx.x; j < n;
         j += stride) {
        atomicAdd(&h[__float2int_rn(pred[j]) * NUM_C + gt[j]], 1u);
    }

    __syncthreads();
    // Flush: two bins per 64-bit global atomic; 148 blocks -> short tail.
    for (int k = threadIdx.x; k < PAIRS; k += HIST_THREADS) {
        unsigned int lo = h[2 * k];
        unsigned int hi = h[2 * k + 1];
        if (lo | hi)
            atomicAdd(&g_counts64[k],
                      (unsigned long long)lo | ((unsigned long long)hi << 32));
    }

    // Fence-free last-block election (release/acquire on the ticket itself).
    __shared__ unsigned int s_last;
    if (threadIdx.x == 0) {
        cuda::atomic_ref<unsigned int, cuda::thread_scope_device> tk(g_ticket);
        s_last = (tk.fetch_add(1u, cuda::memory_order_acq_rel)
                  == (unsigned)gridDim.x - 1u) ? 1u : 0u;
    }
    __syncthreads();
    if (!s_last) return;

    finalize_body(out);
}

extern "C" void kernel_launch(void* const* d_in, const int* in_sizes, int n_in,
                              void* d_out, int out_size) {
    const float* pred = (const float*)d_in[0];
    const int*   gt   = (const int*)d_in[1];
    float* out = (float*)d_out;
    const int n  = in_sizes[0];
    const int n4 = n >> 2;

    fused_kernel<<<HIST_BLOCKS, HIST_THREADS>>>(
        (const float4*)pred, (const int4*)gt, pred, gt, n4, n, out);
}

// round 17
// speedup vs baseline: 2.6404x; 1.0090x over previous
#include <cuda_runtime.h>
#include <cuda_bf16.h>
#include <cuda/atomic>

#define NUM_P 41          // pred labels 0..40
#define NUM_C 26          // gt labels 0..25
#define BINS  (NUM_P * NUM_C)   // 1066
#define PAIRS (BINS / 2)        // 533
#define HIST_BLOCKS 148         // one block per SM
#define HIST_THREADS 1024       // 32 warps -> 1 block/SM regardless of regs

// Global scratch: bin pairs packed into u64 (lo = bin 2k, hi = bin 2k+1).
// Zero at module load; the winning block re-zeroes after use so graph replays
// start clean. Per-bin totals <= 2^24 so no carry crosses the 32-bit boundary.
__device__ unsigned long long g_counts64[PAIRS];
__device__ unsigned int g_ticket;

// Separate ABI allocation: keeps the epilogue's registers/codegen out of the
// hot mainloop. Runs once, on one block, after the ticket election.
__device__ __noinline__ void finalize_body(float* __restrict__ out) {
    __shared__ float        s_pred_sizes[NUM_P];
    __shared__ unsigned int s_omask[NUM_P];
    __shared__ float        s_gt_sizes[NUM_C];
    __shared__ unsigned int s_present;
    __shared__ float        s_dice[64];
    __shared__ float        s_fp[64];

    const int t = threadIdx.x;
    const unsigned int* gc = (const unsigned int*)g_counts64;  // bin k at gc[k]

    if (t < NUM_P) {
        float ps = 0.0f;
        unsigned int m = 0u;
        #pragma unroll
        for (int c = 0; c < NUM_C; c++) {
            unsigned int v = gc[t * NUM_C + c];
            ps += (float)v;
            if (c >= 1 && v) m |= (1u << c);
        }
        s_pred_sizes[t] = ps;
        s_omask[t] = m;
    }
    if (t < NUM_C) {
        float gs = 0.0f;
        #pragma unroll
        for (int p = 0; p < NUM_P; p++)
            gs += (float)gc[p * NUM_C + t];
        s_gt_sizes[t] = gs;
    }
    __syncthreads();

    if (t == 0) {
        unsigned int pm = 0u;
        for (int c = 1; c < NUM_C; c++)
            if (s_gt_sizes[c] > 0.0f) pm |= (1u << c);
        s_present = pm;
    }
    __syncthreads();
    const unsigned int pm = s_present;

    if (t < 64) {
        float contrib = 0.0f;
        if (t >= 1 && t < NUM_C && ((pm >> t) & 1u)) {
            float us = 0.0f;
            #pragma unroll
            for (int p = 0; p < NUM_P; p++)
                if ((s_omask[p] >> t) & 1u) us += s_pred_sizes[p];
            contrib = 2.0f * s_gt_sizes[t] / (us + s_gt_sizes[t] + 1.0f);
        }
        float fpc = 0.0f;
        if (t < NUM_P && s_pred_sizes[t] > 0.0f && (s_omask[t] & pm) == 0u)
            fpc = 1.0f;
        s_dice[t] = contrib;
        s_fp[t]   = fpc;
    }
    __syncthreads();

    if (t == 0) {
        float lesion_dice = 0.0f, fp = 0.0f;
        for (int k = 0; k < 64; k++) { lesion_dice += s_dice[k]; fp += s_fp[k]; }
        float num_gt = (float)__popc(pm);
        out[0] = lesion_dice / (num_gt + fp);
    }
    __syncthreads();

    // Reset scratch for the next graph replay (deterministic across runs).
    for (int k = t; k < PAIRS; k += HIST_THREADS) g_counts64[k] = 0ull;
    if (t == 0) g_ticket = 0u;
}

__global__ void __launch_bounds__(HIST_THREADS)
fused_kernel(const float4* __restrict__ pred4, const int4* __restrict__ gt4,
             const float* __restrict__ pred, const int* __restrict__ gt,
             int n4, int n, float* __restrict__ out) {
    __shared__ unsigned int h[BINS];
    for (int i = threadIdx.x; i < BINS; i += HIST_THREADS) h[i] = 0u;
    __syncthreads();

    const int stride = gridDim.x * HIST_THREADS;
    int i = blockIdx.x * HIST_THREADS + threadIdx.x;

    // Main loop: 2 float4 + 2 int4 loads in flight (MLP ~4), 1 ATOMS/voxel.
    // Measured at the spread-address smem-atomic hardware rate (~2.2 lanes/
    // cyc/SM); no exact encoding with fewer LSU ops per voxel exists.
    for (; i + stride < n4; i += 2 * stride) {
        float4 p0 = pred4[i];
        int4   g0 = gt4[i];
        float4 p1 = pred4[i + stride];
        int4   g1 = gt4[i + stride];
        atomicAdd(&h[__float2int_rn(p0.x) * NUM_C + g0.x], 1u);
        atomicAdd(&h[__float2int_rn(p0.y) * NUM_C + g0.y], 1u);
        atomicAdd(&h[__float2int_rn(p0.z) * NUM_C + g0.z], 1u);
        atomicAdd(&h[__float2int_rn(p0.w) * NUM_C + g0.w], 1u);
        atomicAdd(&h[__float2int_rn(p1.x) * NUM_C + g1.x], 1u);
        atomicAdd(&h[__float2int_rn(p1.y) * NUM_C + g1.y], 1u);
        atomicAdd(&h[__float2int_rn(p1.z) * NUM_C + g1.z], 1u);
        atomicAdd(&h[__float2int_rn(p1.w) * NUM_C + g1.w], 1u);
    }
    for (; i < n4; i += stride) {
        float4 p = pred4[i];
        int4   g = gt4[i];
        atomicAdd(&h[__float2int_rn(p.x) * NUM_C + g.x], 1u);
        atomicAdd(&h[__float2int_rn(p.y) * NUM_C + g.y], 1u);
        atomicAdd(&h[__float2int_rn(p.z) * NUM_C + g.z], 1u);
        atomicAdd(&h[__float2int_rn(p.w) * NUM_C + g.w], 1u);
    }
    int tail_start = n4 * 4;
    for (int j = tail_start + blockIdx.x * HIST_THREADS + threadIdx.x; j < n;
         j += stride) {
        atomicAdd(&h[__float2int_rn(pred[j]) * NUM_C + gt[j]], 1u);
    }

    __syncthreads();
    // Flush: two bins per 64-bit global atomic; 148 blocks -> short tail.
    for (int k = threadIdx.x; k < PAIRS; k += HIST_THREADS) {
        unsigned int lo = h[2 * k];
        unsigned int hi = h[2 * k + 1];
        if (lo | hi)
            atomicAdd(&g_counts64[k],
                      (unsigned long long)lo | ((unsigned long long)hi << 32));
    }

    // Fence-free last-block election (release/acquire on the ticket itself).
    __shared__ unsigned int s_last;
    if (threadIdx.x == 0) {
        cuda::atomic_ref<unsigned int, cuda::thread_scope_device> tk(g_ticket);
        s_last = (tk.fetch_add(1u, cuda::memory_order_acq_rel)
                  == (unsigned)gridDim.x - 1u) ? 1u : 0u;
    }
    __syncthreads();
    if (!s_last) return;

    finalize_body(out);
}

extern "C" void kernel_launch(void* const* d_in, const int* in_sizes, int n_in,
                              void* d_out, int out_size) {
    const float* pred = (const float*)d_in[0];
    const int*   gt   = (const int*)d_in[1];
    float* out = (float*)d_out;
    const int n  = in_sizes[0];
    const int n4 = n >> 2;

    fused_kernel<<<HIST_BLOCKS, HIST_THREADS>>>(
        (const float4*)pred, (const int4*)gt, pred, gt, n4, n, out);
}